// round 6
// baseline (speedup 1.0000x reference)
#include <cuda_runtime.h>
#include <cuda_bf16.h>
#include <cstdint>

using u32 = unsigned int;

// Problem constants: B=16, C=64, H=W=64
static constexpr int B_  = 16;
static constexpr int HW_ = 4096;   // 64*64
static constexpr int SP_ = 1024;   // pooled spatial (32*32)

static constexpr int NWORK  = 256;   // persistent CTAs (<= 2/SM * 148 = 296 resident)
static constexpr int NITEMS = 1280;  // 16 batches * (32 proj + 16 attn + 32 out)
static constexpr int MEGA_SMEM = 82432;  // attn footprint (largest phase)

// ---------------- scratch (__device__ globals; no allocation) ----------------
__device__ __align__(16) __nv_bfloat16 d_theta[B_ * HW_ * 8];   // [b][p][8]
__device__ __align__(16) __nv_bfloat16 d_phi_t[B_ * SP_ * 8];   // [b][s][8]
__device__ __align__(16) __nv_bfloat16 d_g_t  [B_ * 32 * SP_];  // [b][v][s]
__device__ __align__(16) __nv_bfloat16 d_ob16 [B_ * HW_ * 32];  // [b][q][32] normalized, gamma-folded

// dependency flags (reset each call by reset_kernel)
__device__ int g_proj_done[16];     // counts proj items done per batch (target 32)
__device__ int g_attn_done[256];    // flag per (batch, attn-tile)

// ---------------- small helpers ----------------
__device__ __forceinline__ u32 packbf(float lo, float hi) {
    __nv_bfloat162 v = __float22bfloat162_rn(make_float2(lo, hi));
    return *reinterpret_cast<u32*>(&v);
}
__device__ __forceinline__ u32 hmax2u(u32 a, u32 b) {
    __nv_bfloat162 r = __hmax2(*reinterpret_cast<__nv_bfloat162*>(&a),
                               *reinterpret_cast<__nv_bfloat162*>(&b));
    return *reinterpret_cast<u32*>(&r);
}
__device__ __forceinline__ uint4 max4u(uint4 a, uint4 b, uint4 c, uint4 d) {
    uint4 r;
    r.x = hmax2u(hmax2u(a.x, b.x), hmax2u(c.x, d.x));
    r.y = hmax2u(hmax2u(a.y, b.y), hmax2u(c.y, d.y));
    r.z = hmax2u(hmax2u(a.z, b.z), hmax2u(c.z, d.z));
    r.w = hmax2u(hmax2u(a.w, b.w), hmax2u(c.w, d.w));
    return r;
}
// bf16-space Schraudolph exp, two at once: low 16 bits of f are bf16 of exp(x).
// Common-mode bias cancels in softmax. 2 FFMA + 1 PRMT.
__device__ __forceinline__ u32 fexp2pack(float x0, float x1) {
    float f0 = fmaf(x0, 184.6650390625f, 12599162.0f);
    float f1 = fmaf(x1, 184.6650390625f, 12599162.0f);
    return __byte_perm(__float_as_uint(f0), __float_as_uint(f1), 0x5410);
}
// mma.m16n8k8 bf16: S = A(16x8) * B(8x8), C=0
__device__ __forceinline__ void mma_k8(float* d, u32 a0, u32 a1, u32 b0) {
    asm volatile(
        "mma.sync.aligned.m16n8k8.row.col.f32.bf16.bf16.f32 "
        "{%0,%1,%2,%3}, {%4,%5}, {%6}, {%7,%8,%9,%10};\n"
        : "=f"(d[0]), "=f"(d[1]), "=f"(d[2]), "=f"(d[3])
        : "r"(a0), "r"(a1), "r"(b0),
          "f"(0.f), "f"(0.f), "f"(0.f), "f"(0.f));
}
// mma.m16n8k16 bf16: D += A(16x16) * B(16x8)
__device__ __forceinline__ void mma_k16(float* d, u32 a0, u32 a1, u32 a2, u32 a3,
                                        u32 b0, u32 b1) {
    asm volatile(
        "mma.sync.aligned.m16n8k16.row.col.f32.bf16.bf16.f32 "
        "{%0,%1,%2,%3}, {%4,%5,%6,%7}, {%8,%9}, {%0,%1,%2,%3};\n"
        : "+f"(d[0]), "+f"(d[1]), "+f"(d[2]), "+f"(d[3])
        : "r"(a0), "r"(a1), "r"(a2), "r"(a3), "r"(b0), "r"(b1));
}
__device__ __forceinline__ void ldsm_x4(u32& r0, u32& r1, u32& r2, u32& r3, u32 a) {
    asm volatile("ldmatrix.sync.aligned.m8n8.x4.shared.b16 {%0,%1,%2,%3}, [%4];"
                 : "=r"(r0), "=r"(r1), "=r"(r2), "=r"(r3) : "r"(a));
}
__device__ __forceinline__ void ldsm_x4_t(u32& r0, u32& r1, u32& r2, u32& r3, u32 a) {
    asm volatile("ldmatrix.sync.aligned.m8n8.x4.trans.shared.b16 {%0,%1,%2,%3}, [%4];"
                 : "=r"(r0), "=r"(r1), "=r"(r2), "=r"(r3) : "r"(a));
}

// =============== phase 1: projections + fused 2x2 pool (one pooled row) ===============
static constexpr int XS_S = 136;
static constexpr int WS_S = 72;
static constexpr int DS_S = 56;

__device__ __noinline__ void proj_item(
    char* smem, const float* __restrict__ x,
    const float* __restrict__ Wt, const float* __restrict__ Wp,
    const float* __restrict__ Wg, int b, int r, int tid)
{
    __nv_bfloat16* xs  = reinterpret_cast<__nv_bfloat16*>(smem);            // 17408 B
    __nv_bfloat16* Ws  = reinterpret_cast<__nv_bfloat16*>(smem + 17408);    // 6912 B
    __nv_bfloat16* dsm = reinterpret_cast<__nv_bfloat16*>(smem + 24320);    // 14336 B

    int p0 = r * 128;

    // stage W (48x64) packed pairs
    for (int i = tid; i < 1536; i += 256) {
        int j = i >> 5, cp = i & 31;
        const float* Wsrc = (j < 8) ? &Wt[j * 64]
                          : (j < 16) ? &Wp[(j - 8) * 64]
                                     : &Wg[(j - 16) * 64];
        float2 v = *reinterpret_cast<const float2*>(&Wsrc[2 * cp]);
        *reinterpret_cast<u32*>(&Ws[j * WS_S + 2 * cp]) = packbf(v.x, v.y);
    }
    // stage x strip [c][p], packed pairs
    const float* xb = x + (size_t)b * 64 * HW_ + p0;
#pragma unroll
    for (int it = 0; it < 16; it++) {
        int flat = it * 256 + tid;
        int c = flat >> 6, pp = flat & 63;
        float2 v = *reinterpret_cast<const float2*>(&xb[(size_t)c * HW_ + 2 * pp]);
        *reinterpret_cast<u32*>(&xs[c * XS_S + 2 * pp]) = packbf(v.x, v.y);
    }
    __syncthreads();

    int w = tid >> 5, lane = tid & 31;
    int g4 = lane >> 2, tg = lane & 3;
    int pw = w * 16;

    int mi = lane >> 3, rr = lane & 7;
    int half8 = (mi & 1) * 8;
    int oth8  = (mi >> 1) * 8;
    u32 xs_a = (u32)__cvta_generic_to_shared(xs);
    u32 ws_a = (u32)__cvta_generic_to_shared(Ws);
    u32 b_base = xs_a + ((half8 + rr) * XS_S + pw + oth8) * 2;

    float acc[3][2][4];
#pragma unroll
    for (int m = 0; m < 3; m++)
#pragma unroll
        for (int n = 0; n < 2; n++)
#pragma unroll
            for (int e = 0; e < 4; e++) acc[m][n][e] = 0.f;

#pragma unroll
    for (int ks = 0; ks < 4; ks++) {
        int k0 = ks * 16;
        u32 b0n0, b1n0, b0n1, b1n1;
        ldsm_x4_t(b0n0, b1n0, b0n1, b1n1, b_base + k0 * XS_S * 2);
#pragma unroll
        for (int m = 0; m < 3; m++) {
            u32 A0, A1, A2, A3;
            ldsm_x4(A0, A1, A2, A3,
                    ws_a + ((m * 16 + half8 + rr) * WS_S + k0 + oth8) * 2);
            mma_k16(acc[m][0], A0, A1, A2, A3, b0n0, b1n0);
            mma_k16(acc[m][1], A0, A1, A2, A3, b0n1, b1n1);
        }
    }

#pragma unroll
    for (int m = 0; m < 3; m++)
#pragma unroll
        for (int nt = 0; nt < 2; nt++) {
            int j = m * 16 + g4;
            int p = pw + nt * 8 + 2 * tg;
            dsm[p * DS_S + j]           = __float2bfloat16(acc[m][nt][0]);
            dsm[(p + 1) * DS_S + j]     = __float2bfloat16(acc[m][nt][1]);
            dsm[p * DS_S + j + 8]       = __float2bfloat16(acc[m][nt][2]);
            dsm[(p + 1) * DS_S + j + 8] = __float2bfloat16(acc[m][nt][3]);
        }
    __syncthreads();

    if (tid < 128) {
        reinterpret_cast<uint4*>(d_theta)[(size_t)b * HW_ + p0 + tid] =
            *reinterpret_cast<const uint4*>(&dsm[tid * DS_S]);
        if (tid >= 96) {
            int j2 = tid - 96;
            int pA = 2 * j2, pC = 64 + 2 * j2;
            uint4 m = max4u(*reinterpret_cast<const uint4*>(&dsm[pA * DS_S + 8]),
                            *reinterpret_cast<const uint4*>(&dsm[(pA + 1) * DS_S + 8]),
                            *reinterpret_cast<const uint4*>(&dsm[pC * DS_S + 8]),
                            *reinterpret_cast<const uint4*>(&dsm[(pC + 1) * DS_S + 8]));
            reinterpret_cast<uint4*>(d_phi_t)[(size_t)b * SP_ + r * 32 + j2] = m;
        }
    } else {
        int i  = tid - 128;
        int j2 = i & 31, vq = i >> 5;
        int pA = 2 * j2, pC = 64 + 2 * j2;
        int off = 16 + 8 * vq;
        uint4 m = max4u(*reinterpret_cast<const uint4*>(&dsm[pA * DS_S + off]),
                        *reinterpret_cast<const uint4*>(&dsm[(pA + 1) * DS_S + off]),
                        *reinterpret_cast<const uint4*>(&dsm[pC * DS_S + off]),
                        *reinterpret_cast<const uint4*>(&dsm[(pC + 1) * DS_S + off]));
        int s = r * 32 + j2;
        __nv_bfloat16* gt = d_g_t + ((size_t)b * 32 << 10) + s;
        const __nv_bfloat162* h = reinterpret_cast<const __nv_bfloat162*>(&m);
#pragma unroll
        for (int e = 0; e < 4; e++) {
            int v = vq * 8 + 2 * e;
            gt[(size_t)v << 10]       = h[e].x;
            gt[(size_t)(v + 1) << 10] = h[e].y;
        }
    }
}

// =============== phase 2: fused attention (256 queries per item) ===============
static constexpr int G_STRIDE = 1032;

__device__ __noinline__ void attn_item(
    char* smem, const float* __restrict__ gamma_p, int b, int a, int tid)
{
    __nv_bfloat16* phi_s = reinterpret_cast<__nv_bfloat16*>(smem);                 // 16384 B
    __nv_bfloat16* g_s   = reinterpret_cast<__nv_bfloat16*>(smem + SP_ * 8 * 2);   // 66048 B

    {
        const uint4* src = reinterpret_cast<const uint4*>(d_phi_t) + (size_t)b * SP_;
        uint4* dst = reinterpret_cast<uint4*>(phi_s);
        for (int i = tid; i < SP_; i += 256) dst[i] = src[i];
    }
    {
        const uint4* src = reinterpret_cast<const uint4*>(d_g_t) + (size_t)b * 32 * 128;
        uint4* dst = reinterpret_cast<uint4*>(g_s);
        for (int i = tid; i < 32 * 128; i += 256) {
            int v = i >> 7, col = i & 127;
            dst[v * 129 + col] = src[i];
        }
    }
    __syncthreads();

    int w    = tid >> 5;
    int lane = tid & 31;
    int g4   = lane >> 2;
    int tg   = lane & 3;
    int qb   = a * 256 + w * 32;
    int q0   = qb + g4;
    int q1   = qb + 16 + g4;

    const __nv_bfloat16* th = d_theta + (size_t)(b * HW_) * 8;
    u32 a0 = *reinterpret_cast<const u32*>(th + (size_t)q0 * 8 + 2 * tg);
    u32 a1 = *reinterpret_cast<const u32*>(th + (size_t)(q0 + 8) * 8 + 2 * tg);
    u32 a2 = *reinterpret_cast<const u32*>(th + (size_t)q1 * 8 + 2 * tg);
    u32 a3 = *reinterpret_cast<const u32*>(th + (size_t)(q1 + 8) * 8 + 2 * tg);

    const u32 ONES = 0x3F803F80u;

    float o0[16], o1[16];
#pragma unroll
    for (int i = 0; i < 16; i++) { o0[i] = 0.f; o1[i] = 0.f; }
    float sm0[4] = {0.f, 0.f, 0.f, 0.f};
    float sm1[4] = {0.f, 0.f, 0.f, 0.f};

#pragma unroll 2
    for (int kb = 0; kb < SP_; kb += 16) {
        u32 pb0 = *reinterpret_cast<const u32*>(phi_s + (kb + g4) * 8 + 2 * tg);
        u32 pb1 = *reinterpret_cast<const u32*>(phi_s + (kb + 8 + g4) * 8 + 2 * tg);

        float t0s1[4], t0s2[4], t1s1[4], t1s2[4];
        mma_k8(t0s1, a0, a1, pb0);
        mma_k8(t0s2, a0, a1, pb1);
        mma_k8(t1s1, a2, a3, pb0);
        mma_k8(t1s2, a2, a3, pb1);

        u32 pa0 = fexp2pack(t0s1[0], t0s1[1]);
        u32 pa1 = fexp2pack(t0s1[2], t0s1[3]);
        u32 pa2 = fexp2pack(t0s2[0], t0s2[1]);
        u32 pa3 = fexp2pack(t0s2[2], t0s2[3]);
        u32 qa0 = fexp2pack(t1s1[0], t1s1[1]);
        u32 qa1 = fexp2pack(t1s1[2], t1s1[3]);
        u32 qa2 = fexp2pack(t1s2[0], t1s2[1]);
        u32 qa3 = fexp2pack(t1s2[2], t1s2[3]);

        mma_k16(sm0, pa0, pa1, pa2, pa3, ONES, ONES);
        mma_k16(sm1, qa0, qa1, qa2, qa3, ONES, ONES);

        const __nv_bfloat16* grow = g_s + g4 * G_STRIDE + kb + 2 * tg;
#pragma unroll
        for (int j = 0; j < 4; j++) {
            u32 gb0 = *reinterpret_cast<const u32*>(grow + j * 8 * G_STRIDE);
            u32 gb1 = *reinterpret_cast<const u32*>(grow + j * 8 * G_STRIDE + 8);
            mma_k16(&o0[4 * j], pa0, pa1, pa2, pa3, gb0, gb1);
            mma_k16(&o1[4 * j], qa0, qa1, qa2, qa3, gb0, gb1);
        }
    }

    float gm = *gamma_p;
    float iA0 = __fdividef(gm, sm0[0]);
    float iA1 = __fdividef(gm, sm0[2]);
    float iB0 = __fdividef(gm, sm1[0]);
    float iB1 = __fdividef(gm, sm1[2]);

    __nv_bfloat16* ob = d_ob16 + (size_t)(b * HW_) * 32;
#pragma unroll
    for (int j = 0; j < 4; j++) {
        int v = 8 * j + 2 * tg;
        *reinterpret_cast<u32*>(&ob[(size_t)q0 * 32 + v]) =
            packbf(o0[4 * j + 0] * iA0, o0[4 * j + 1] * iA0);
        *reinterpret_cast<u32*>(&ob[(size_t)(q0 + 8) * 32 + v]) =
            packbf(o0[4 * j + 2] * iA1, o0[4 * j + 3] * iA1);
        *reinterpret_cast<u32*>(&ob[(size_t)q1 * 32 + v]) =
            packbf(o1[4 * j + 0] * iB0, o1[4 * j + 1] * iB0);
        *reinterpret_cast<u32*>(&ob[(size_t)(q1 + 8) * 32 + v]) =
            packbf(o1[4 * j + 2] * iB1, o1[4 * j + 3] * iB1);
    }
}

// =============== phase 3: out = Wo @ o' + x (128 pixels per item) ===============
static constexpr int WO_S = 34;

__device__ __noinline__ void out_item(
    char* smem, const float* __restrict__ x, const float* __restrict__ Wo,
    float* __restrict__ out, int b, int t, int tid)
{
    __nv_bfloat16* wsm = reinterpret_cast<__nv_bfloat16*>(smem);   // 4352 B

    int p0 = t * 128;
    int w = tid >> 5, lane = tid & 31;
    int g4 = lane >> 2, tg = lane & 3;
    int pw = w * 16;

    const __nv_bfloat16* obp = d_ob16 + ((size_t)(b * HW_ + p0 + pw)) * 32;
    u32 Bf[2][2][2];
#pragma unroll
    for (int nt = 0; nt < 2; nt++) {
        const __nv_bfloat16* rr = obp + (nt * 8 + g4) * 32;
#pragma unroll
        for (int ks = 0; ks < 2; ks++) {
            Bf[nt][ks][0] = *reinterpret_cast<const u32*>(rr + ks * 16 + 2 * tg);
            Bf[nt][ks][1] = *reinterpret_cast<const u32*>(rr + ks * 16 + 8 + 2 * tg);
        }
    }
    const float* xb = x + (size_t)b * 64 * HW_;
    float2 xv[4][2][2];
#pragma unroll
    for (int m = 0; m < 4; m++)
#pragma unroll
        for (int nt = 0; nt < 2; nt++) {
            int p = p0 + pw + nt * 8 + 2 * tg;
            xv[m][nt][0] = *reinterpret_cast<const float2*>(&xb[(size_t)(m * 16 + g4) * HW_ + p]);
            xv[m][nt][1] = *reinterpret_cast<const float2*>(&xb[(size_t)(m * 16 + g4 + 8) * HW_ + p]);
        }

    for (int i = tid; i < 64 * 32; i += 256) {
        int c = i >> 5, v = i & 31;
        wsm[c * WO_S + v] = __float2bfloat16(Wo[c * 32 + v]);
    }
    __syncthreads();

    float acc[4][2][4];
#pragma unroll
    for (int m = 0; m < 4; m++)
#pragma unroll
        for (int n = 0; n < 2; n++)
#pragma unroll
            for (int e = 0; e < 4; e++) acc[m][n][e] = 0.f;

#pragma unroll
    for (int ks = 0; ks < 2; ks++) {
        u32 A[4][4];
#pragma unroll
        for (int m = 0; m < 4; m++) {
            int r0 = (m * 16 + g4) * WO_S + ks * 16 + 2 * tg;
            int r1 = (m * 16 + g4 + 8) * WO_S + ks * 16 + 2 * tg;
            A[m][0] = *reinterpret_cast<const u32*>(&wsm[r0]);
            A[m][1] = *reinterpret_cast<const u32*>(&wsm[r1]);
            A[m][2] = *reinterpret_cast<const u32*>(&wsm[r0 + 8]);
            A[m][3] = *reinterpret_cast<const u32*>(&wsm[r1 + 8]);
        }
#pragma unroll
        for (int nt = 0; nt < 2; nt++)
#pragma unroll
            for (int m = 0; m < 4; m++)
                mma_k16(acc[m][nt], A[m][0], A[m][1], A[m][2], A[m][3],
                        Bf[nt][ks][0], Bf[nt][ks][1]);
    }

    float* outb = out + (size_t)b * 64 * HW_;
#pragma unroll
    for (int m = 0; m < 4; m++)
#pragma unroll
        for (int nt = 0; nt < 2; nt++) {
            int c = m * 16 + g4;
            int p = p0 + pw + nt * 8 + 2 * tg;
            size_t o1 = (size_t)c * HW_ + p;
            size_t o2 = (size_t)(c + 8) * HW_ + p;
            float2 r1 = make_float2(acc[m][nt][0] + xv[m][nt][0].x,
                                    acc[m][nt][1] + xv[m][nt][0].y);
            float2 r2 = make_float2(acc[m][nt][2] + xv[m][nt][1].x,
                                    acc[m][nt][3] + xv[m][nt][1].y);
            *reinterpret_cast<float2*>(&outb[o1]) = r1;
            *reinterpret_cast<float2*>(&outb[o2]) = r2;
        }
}

// =============== reset + megakernel ===============
__global__ void reset_kernel()
{
    int i = threadIdx.x;
    if (i < 16) g_proj_done[i] = 0;
    g_attn_done[i] = 0;
}

// Item order per batch: [proj r=0..31][attn a=0..15][out t=0..31].
// Static schedule: worker w executes items w, w+NWORK, ... (all workers resident:
// 2 CTAs/SM * 148 SMs = 296 >= NWORK). Every wait targets a smaller global index.
__global__ void __launch_bounds__(256, 2) mega_kernel(
    const float* __restrict__ x,
    const float* __restrict__ Wt, const float* __restrict__ Wp,
    const float* __restrict__ Wg, const float* __restrict__ Wo,
    const float* __restrict__ gamma_p, float* __restrict__ out)
{
    extern __shared__ __align__(16) char smem[];
    int tid = threadIdx.x;

    for (int g = blockIdx.x; g < NITEMS; g += NWORK) {
        int b = g / 80;
        int r = g - b * 80;

        if (r < 32) {
            // ---- proj item ----
            proj_item(smem, x, Wt, Wp, Wg, b, r, tid);
            __syncthreads();
            if (tid == 0) {
                __threadfence();
                atomicAdd(&g_proj_done[b], 1);
            }
            __syncthreads();
        } else if (r < 48) {
            // ---- attn item ----
            int a = r - 32;
            if (tid == 0) {
                while (atomicAdd(&g_proj_done[b], 0) < 32) __nanosleep(128);
                __threadfence();
            }
            __syncthreads();
            attn_item(smem, gamma_p, b, a, tid);
            __syncthreads();
            if (tid == 0) {
                __threadfence();
                atomicExch(&g_attn_done[b * 16 + a], 1);
            }
            __syncthreads();
        } else {
            // ---- out item ----
            int t = r - 48;
            int a = t >> 1;
            if (tid == 0) {
                while (atomicAdd(&g_attn_done[b * 16 + a], 0) == 0) __nanosleep(128);
                __threadfence();
            }
            __syncthreads();
            out_item(smem, x, Wo, out, b, t, tid);
            __syncthreads();
        }
    }
}

// ---------------- launch ----------------
extern "C" void kernel_launch(void* const* d_in, const int* in_sizes, int n_in,
                              void* d_out, int out_size)
{
    const float* x     = (const float*)d_in[0];
    const float* Wt    = (const float*)d_in[1];
    const float* Wp    = (const float*)d_in[2];
    const float* Wg    = (const float*)d_in[3];
    const float* Wo    = (const float*)d_in[4];
    const float* gamma = (const float*)d_in[5];
    float* out = (float*)d_out;

    reset_kernel<<<1, 256>>>();

    cudaFuncSetAttribute(mega_kernel, cudaFuncAttributeMaxDynamicSharedMemorySize, MEGA_SMEM);
    mega_kernel<<<NWORK, 256, MEGA_SMEM>>>(x, Wt, Wp, Wg, Wo, gamma, out);
}

// round 7
// speedup vs baseline: 2.5149x; 2.5149x over previous
#include <cuda_runtime.h>
#include <cuda_bf16.h>
#include <cstdint>

using u32 = unsigned int;

// Problem constants: B=16, C=64, H=W=64
static constexpr int B_  = 16;
static constexpr int HW_ = 4096;   // 64*64
static constexpr int SP_ = 1024;   // pooled spatial (32*32)

// ---------------- scratch (__device__ globals; no allocation) ----------------
__device__ __align__(16) __nv_bfloat16 d_theta[B_ * HW_ * 8];   // [b][p][8]
__device__ __align__(16) __nv_bfloat16 d_phi_t[B_ * SP_ * 8];   // [b][s][8]
__device__ __align__(16) __nv_bfloat16 d_g_t  [B_ * 32 * SP_];  // [b][v][s]

// ---------------- small helpers ----------------
__device__ __forceinline__ u32 packbf(float lo, float hi) {
    __nv_bfloat162 v = __float22bfloat162_rn(make_float2(lo, hi));
    return *reinterpret_cast<u32*>(&v);
}
__device__ __forceinline__ u32 hmax2u(u32 a, u32 b) {
    __nv_bfloat162 r = __hmax2(*reinterpret_cast<__nv_bfloat162*>(&a),
                               *reinterpret_cast<__nv_bfloat162*>(&b));
    return *reinterpret_cast<u32*>(&r);
}
__device__ __forceinline__ uint4 max4u(uint4 a, uint4 b, uint4 c, uint4 d) {
    uint4 r;
    r.x = hmax2u(hmax2u(a.x, b.x), hmax2u(c.x, d.x));
    r.y = hmax2u(hmax2u(a.y, b.y), hmax2u(c.y, d.y));
    r.z = hmax2u(hmax2u(a.z, b.z), hmax2u(c.z, d.z));
    r.w = hmax2u(hmax2u(a.w, b.w), hmax2u(c.w, d.w));
    return r;
}
// bf16-space Schraudolph exp, two at once: low 16 bits of f are bf16 of exp(x).
// Common-mode bias cancels in softmax. 2 FFMA + 1 PRMT.
__device__ __forceinline__ u32 fexp2pack(float x0, float x1) {
    float f0 = fmaf(x0, 184.6650390625f, 12599162.0f);
    float f1 = fmaf(x1, 184.6650390625f, 12599162.0f);
    return __byte_perm(__float_as_uint(f0), __float_as_uint(f1), 0x5410);
}
// mma.m16n8k8 bf16: S = A(16x8) * B(8x8), C=0
__device__ __forceinline__ void mma_k8(float* d, u32 a0, u32 a1, u32 b0) {
    asm volatile(
        "mma.sync.aligned.m16n8k8.row.col.f32.bf16.bf16.f32 "
        "{%0,%1,%2,%3}, {%4,%5}, {%6}, {%7,%8,%9,%10};\n"
        : "=f"(d[0]), "=f"(d[1]), "=f"(d[2]), "=f"(d[3])
        : "r"(a0), "r"(a1), "r"(b0),
          "f"(0.f), "f"(0.f), "f"(0.f), "f"(0.f));
}
// mma.m16n8k16 bf16: D += A(16x16) * B(16x8)
__device__ __forceinline__ void mma_k16(float* d, u32 a0, u32 a1, u32 a2, u32 a3,
                                        u32 b0, u32 b1) {
    asm volatile(
        "mma.sync.aligned.m16n8k16.row.col.f32.bf16.bf16.f32 "
        "{%0,%1,%2,%3}, {%4,%5,%6,%7}, {%8,%9}, {%0,%1,%2,%3};\n"
        : "+f"(d[0]), "+f"(d[1]), "+f"(d[2]), "+f"(d[3])
        : "r"(a0), "r"(a1), "r"(a2), "r"(a3), "r"(b0), "r"(b1));
}
__device__ __forceinline__ void ldsm_x4(u32& r0, u32& r1, u32& r2, u32& r3, u32 a) {
    asm volatile("ldmatrix.sync.aligned.m8n8.x4.shared.b16 {%0,%1,%2,%3}, [%4];"
                 : "=r"(r0), "=r"(r1), "=r"(r2), "=r"(r3) : "r"(a));
}
__device__ __forceinline__ void ldsm_x4_t(u32& r0, u32& r1, u32& r2, u32& r3, u32 a) {
    asm volatile("ldmatrix.sync.aligned.m8n8.x4.trans.shared.b16 {%0,%1,%2,%3}, [%4];"
                 : "=r"(r0), "=r"(r1), "=r"(r2), "=r"(r3) : "r"(a));
}

// ---------------- kernel 1: projections (tensor cores) + fused 2x2 pool ----------------
// CTA handles 128 pixels = 2 image rows = 1 pooled row. grid (32,16) x 256.
static constexpr int XS_S = 136;
static constexpr int WS_S = 72;
static constexpr int DS_S = 56;

__global__ void __launch_bounds__(256) proj_kernel(
    const float* __restrict__ x,
    const float* __restrict__ Wt, const float* __restrict__ Wp,
    const float* __restrict__ Wg)
{
    __shared__ __align__(16) __nv_bfloat16 xs [64 * XS_S];
    __shared__ __align__(16) __nv_bfloat16 Ws [48 * WS_S];
    __shared__ __align__(16) __nv_bfloat16 dsm[128 * DS_S];

    int tid = threadIdx.x;
    int b   = blockIdx.y;
    int r   = blockIdx.x;          // pooled row
    int p0  = r * 128;

    // stage W (48x64) packed pairs
    for (int i = tid; i < 1536; i += 256) {
        int j = i >> 5, cp = i & 31;
        const float* Wsrc = (j < 8) ? &Wt[j * 64]
                          : (j < 16) ? &Wp[(j - 8) * 64]
                                     : &Wg[(j - 16) * 64];
        float2 v = *reinterpret_cast<const float2*>(&Wsrc[2 * cp]);
        *reinterpret_cast<u32*>(&Ws[j * WS_S + 2 * cp]) = packbf(v.x, v.y);
    }
    // stage x strip [c][p], packed pairs
    const float* xb = x + (size_t)b * 64 * HW_ + p0;
#pragma unroll
    for (int it = 0; it < 16; it++) {
        int flat = it * 256 + tid;
        int c = flat >> 6, pp = flat & 63;
        float2 v = *reinterpret_cast<const float2*>(&xb[(size_t)c * HW_ + 2 * pp]);
        *reinterpret_cast<u32*>(&xs[c * XS_S + 2 * pp]) = packbf(v.x, v.y);
    }
    __syncthreads();

    int w = tid >> 5, lane = tid & 31;
    int g4 = lane >> 2, tg = lane & 3;
    int pw = w * 16;

    int mi = lane >> 3, rr = lane & 7;
    int half8 = (mi & 1) * 8;
    int oth8  = (mi >> 1) * 8;
    u32 xs_a = (u32)__cvta_generic_to_shared(xs);
    u32 ws_a = (u32)__cvta_generic_to_shared(Ws);
    u32 b_base = xs_a + ((half8 + rr) * XS_S + pw + oth8) * 2;

    float acc[3][2][4];
#pragma unroll
    for (int m = 0; m < 3; m++)
#pragma unroll
        for (int n = 0; n < 2; n++)
#pragma unroll
            for (int e = 0; e < 4; e++) acc[m][n][e] = 0.f;

#pragma unroll
    for (int ks = 0; ks < 4; ks++) {
        int k0 = ks * 16;
        u32 b0n0, b1n0, b0n1, b1n1;
        ldsm_x4_t(b0n0, b1n0, b0n1, b1n1, b_base + k0 * XS_S * 2);
#pragma unroll
        for (int m = 0; m < 3; m++) {
            u32 A0, A1, A2, A3;
            ldsm_x4(A0, A1, A2, A3,
                    ws_a + ((m * 16 + half8 + rr) * WS_S + k0 + oth8) * 2);
            mma_k16(acc[m][0], A0, A1, A2, A3, b0n0, b1n0);
            mma_k16(acc[m][1], A0, A1, A2, A3, b0n1, b1n1);
        }
    }

#pragma unroll
    for (int m = 0; m < 3; m++)
#pragma unroll
        for (int nt = 0; nt < 2; nt++) {
            int j = m * 16 + g4;
            int p = pw + nt * 8 + 2 * tg;
            dsm[p * DS_S + j]           = __float2bfloat16(acc[m][nt][0]);
            dsm[(p + 1) * DS_S + j]     = __float2bfloat16(acc[m][nt][1]);
            dsm[p * DS_S + j + 8]       = __float2bfloat16(acc[m][nt][2]);
            dsm[(p + 1) * DS_S + j + 8] = __float2bfloat16(acc[m][nt][3]);
        }
    __syncthreads();

    if (tid < 128) {
        reinterpret_cast<uint4*>(d_theta)[(size_t)b * HW_ + p0 + tid] =
            *reinterpret_cast<const uint4*>(&dsm[tid * DS_S]);
        if (tid >= 96) {
            int j2 = tid - 96;
            int pA = 2 * j2, pC = 64 + 2 * j2;
            uint4 m = max4u(*reinterpret_cast<const uint4*>(&dsm[pA * DS_S + 8]),
                            *reinterpret_cast<const uint4*>(&dsm[(pA + 1) * DS_S + 8]),
                            *reinterpret_cast<const uint4*>(&dsm[pC * DS_S + 8]),
                            *reinterpret_cast<const uint4*>(&dsm[(pC + 1) * DS_S + 8]));
            reinterpret_cast<uint4*>(d_phi_t)[(size_t)b * SP_ + r * 32 + j2] = m;
        }
    } else {
        int i  = tid - 128;
        int j2 = i & 31, vq = i >> 5;
        int pA = 2 * j2, pC = 64 + 2 * j2;
        int off = 16 + 8 * vq;
        uint4 m = max4u(*reinterpret_cast<const uint4*>(&dsm[pA * DS_S + off]),
                        *reinterpret_cast<const uint4*>(&dsm[(pA + 1) * DS_S + off]),
                        *reinterpret_cast<const uint4*>(&dsm[pC * DS_S + off]),
                        *reinterpret_cast<const uint4*>(&dsm[(pC + 1) * DS_S + off]));
        int s = r * 32 + j2;
        __nv_bfloat16* gt = d_g_t + ((size_t)b * 32 << 10) + s;
        const __nv_bfloat162* h = reinterpret_cast<const __nv_bfloat162*>(&m);
#pragma unroll
        for (int e = 0; e < 4; e++) {
            int v = vq * 8 + 2 * e;
            gt[(size_t)v << 10]       = h[e].x;
            gt[(size_t)(v + 1) << 10] = h[e].y;
        }
    }
}

// ---------------- kernel 2: fused attention + output projection + residual ----------------
// 256 queries/CTA. After the key loop, o is staged in smem (overlaying phi) and the
// CTA-local out-GEMM (Wo @ o^T + x) runs as an epilogue. grid (16,16) x 256.
static constexpr int G_STRIDE = 1032;
static constexpr int ATTN_SMEM = SP_ * 8 * 2 + 32 * G_STRIDE * 2;  // 82432
static constexpr int OSM_S = 40;   // o stage stride (halfwords), conflict-free
static constexpr int WO_S  = 34;   // Wo stage stride

__global__ void __launch_bounds__(256, 2) attn_out_kernel(
    const float* __restrict__ x, const float* __restrict__ Wo,
    const float* __restrict__ gamma_p, float* __restrict__ out)
{
    extern __shared__ __align__(16) char smem[];
    __nv_bfloat16* phi_s = reinterpret_cast<__nv_bfloat16*>(smem);
    __nv_bfloat16* g_s   = reinterpret_cast<__nv_bfloat16*>(smem + SP_ * 8 * 2);
    // epilogue overlays (valid only after the key loop):
    __nv_bfloat16* osm = reinterpret_cast<__nv_bfloat16*>(smem);            // 256*40*2 = 20480 B
    __nv_bfloat16* wsm = reinterpret_cast<__nv_bfloat16*>(smem + 20480);    // 64*34*2  =  4352 B

    int b   = blockIdx.y;
    int tid = threadIdx.x;

    {
        const uint4* src = reinterpret_cast<const uint4*>(d_phi_t) + (size_t)b * SP_;
        uint4* dst = reinterpret_cast<uint4*>(phi_s);
        for (int i = tid; i < SP_; i += 256) dst[i] = src[i];
    }
    {
        const uint4* src = reinterpret_cast<const uint4*>(d_g_t) + (size_t)b * 32 * 128;
        uint4* dst = reinterpret_cast<uint4*>(g_s);
        for (int i = tid; i < 32 * 128; i += 256) {
            int v = i >> 7, col = i & 127;
            dst[v * 129 + col] = src[i];
        }
    }
    __syncthreads();

    int w    = tid >> 5;
    int lane = tid & 31;
    int g4   = lane >> 2;
    int tg   = lane & 3;
    int qb   = blockIdx.x * 256 + w * 32;   // 2 q-tiles per warp
    int q0   = qb + g4;
    int q1   = qb + 16 + g4;

    const __nv_bfloat16* th = d_theta + (size_t)(b * HW_) * 8;
    u32 a0 = *reinterpret_cast<const u32*>(th + (size_t)q0 * 8 + 2 * tg);
    u32 a1 = *reinterpret_cast<const u32*>(th + (size_t)(q0 + 8) * 8 + 2 * tg);
    u32 a2 = *reinterpret_cast<const u32*>(th + (size_t)q1 * 8 + 2 * tg);
    u32 a3 = *reinterpret_cast<const u32*>(th + (size_t)(q1 + 8) * 8 + 2 * tg);

    const u32 ONES = 0x3F803F80u;

    float o0[16], o1[16];
#pragma unroll
    for (int i = 0; i < 16; i++) { o0[i] = 0.f; o1[i] = 0.f; }
    float sm0[4] = {0.f, 0.f, 0.f, 0.f};
    float sm1[4] = {0.f, 0.f, 0.f, 0.f};

#pragma unroll 2
    for (int kb = 0; kb < SP_; kb += 16) {
        u32 pb0 = *reinterpret_cast<const u32*>(phi_s + (kb + g4) * 8 + 2 * tg);
        u32 pb1 = *reinterpret_cast<const u32*>(phi_s + (kb + 8 + g4) * 8 + 2 * tg);

        float t0s1[4], t0s2[4], t1s1[4], t1s2[4];
        mma_k8(t0s1, a0, a1, pb0);
        mma_k8(t0s2, a0, a1, pb1);
        mma_k8(t1s1, a2, a3, pb0);
        mma_k8(t1s2, a2, a3, pb1);

        u32 pa0 = fexp2pack(t0s1[0], t0s1[1]);
        u32 pa1 = fexp2pack(t0s1[2], t0s1[3]);
        u32 pa2 = fexp2pack(t0s2[0], t0s2[1]);
        u32 pa3 = fexp2pack(t0s2[2], t0s2[3]);
        u32 qa0 = fexp2pack(t1s1[0], t1s1[1]);
        u32 qa1 = fexp2pack(t1s1[2], t1s1[3]);
        u32 qa2 = fexp2pack(t1s2[0], t1s2[1]);
        u32 qa3 = fexp2pack(t1s2[2], t1s2[3]);

        mma_k16(sm0, pa0, pa1, pa2, pa3, ONES, ONES);
        mma_k16(sm1, qa0, qa1, qa2, qa3, ONES, ONES);

        const __nv_bfloat16* grow = g_s + g4 * G_STRIDE + kb + 2 * tg;
#pragma unroll
        for (int j = 0; j < 4; j++) {
            u32 gb0 = *reinterpret_cast<const u32*>(grow + j * 8 * G_STRIDE);
            u32 gb1 = *reinterpret_cast<const u32*>(grow + j * 8 * G_STRIDE + 8);
            mma_k16(&o0[4 * j], pa0, pa1, pa2, pa3, gb0, gb1);
            mma_k16(&o1[4 * j], qa0, qa1, qa2, qa3, gb0, gb1);
        }
    }

    float gm = *gamma_p;
    float iA0 = __fdividef(gm, sm0[0]);
    float iA1 = __fdividef(gm, sm0[2]);
    float iB0 = __fdividef(gm, sm1[0]);
    float iB1 = __fdividef(gm, sm1[2]);

    // ---- stage normalized, gamma-folded o into smem (overlay phi region) ----
    __syncthreads();   // all warps done reading phi_s/g_s
    {
        int ql0 = w * 32 + g4;        // local q of tile 0
        int ql1 = w * 32 + 16 + g4;   // local q of tile 1
#pragma unroll
        for (int j = 0; j < 4; j++) {
            int v = 8 * j + 2 * tg;
            *reinterpret_cast<u32*>(&osm[ql0 * OSM_S + v]) =
                packbf(o0[4 * j + 0] * iA0, o0[4 * j + 1] * iA0);
            *reinterpret_cast<u32*>(&osm[(ql0 + 8) * OSM_S + v]) =
                packbf(o0[4 * j + 2] * iA1, o0[4 * j + 3] * iA1);
            *reinterpret_cast<u32*>(&osm[ql1 * OSM_S + v]) =
                packbf(o1[4 * j + 0] * iB0, o1[4 * j + 1] * iB0);
            *reinterpret_cast<u32*>(&osm[(ql1 + 8) * OSM_S + v]) =
                packbf(o1[4 * j + 2] * iB1, o1[4 * j + 3] * iB1);
        }
    }
    // stage Wo
    for (int i = tid; i < 64 * 32; i += 256) {
        int c = i >> 5, v = i & 31;
        wsm[c * WO_S + v] = __float2bfloat16(Wo[c * 32 + v]);
    }
    __syncthreads();

    // ---- epilogue: out[c][p] = Wo @ o^T + x, CTA covers 256 pixels ----
    int p0 = blockIdx.x * 256;
    const float* xb = x + (size_t)b * 64 * HW_;
    float* outb     = out + (size_t)b * 64 * HW_;

    // A fragments (Wo), loaded once
    u32 A[2][4][4];
#pragma unroll
    for (int ks = 0; ks < 2; ks++)
#pragma unroll
        for (int m = 0; m < 4; m++) {
            int r0 = (m * 16 + g4) * WO_S + ks * 16 + 2 * tg;
            int r1 = (m * 16 + g4 + 8) * WO_S + ks * 16 + 2 * tg;
            A[ks][m][0] = *reinterpret_cast<const u32*>(&wsm[r0]);
            A[ks][m][1] = *reinterpret_cast<const u32*>(&wsm[r1]);
            A[ks][m][2] = *reinterpret_cast<const u32*>(&wsm[r0 + 8]);
            A[ks][m][3] = *reinterpret_cast<const u32*>(&wsm[r1 + 8]);
        }

#pragma unroll
    for (int h = 0; h < 2; h++) {
        int ph = w * 32 + h * 16;   // local pixel base for this half (16 pixels)

        // B fragments from osm
        u32 Bf[2][2][2];
#pragma unroll
        for (int nt = 0; nt < 2; nt++) {
            int qr = (ph + nt * 8 + g4) * OSM_S;
#pragma unroll
            for (int ks = 0; ks < 2; ks++) {
                Bf[nt][ks][0] = *reinterpret_cast<const u32*>(&osm[qr + ks * 16 + 2 * tg]);
                Bf[nt][ks][1] = *reinterpret_cast<const u32*>(&osm[qr + ks * 16 + 8 + 2 * tg]);
            }
        }
        // prefetch x residual
        float2 xv[4][2][2];
#pragma unroll
        for (int m = 0; m < 4; m++)
#pragma unroll
            for (int nt = 0; nt < 2; nt++) {
                int p = p0 + ph + nt * 8 + 2 * tg;
                xv[m][nt][0] = *reinterpret_cast<const float2*>(&xb[(size_t)(m * 16 + g4) * HW_ + p]);
                xv[m][nt][1] = *reinterpret_cast<const float2*>(&xb[(size_t)(m * 16 + g4 + 8) * HW_ + p]);
            }

        float acc[4][2][4];
#pragma unroll
        for (int m = 0; m < 4; m++)
#pragma unroll
            for (int n = 0; n < 2; n++)
#pragma unroll
                for (int e = 0; e < 4; e++) acc[m][n][e] = 0.f;

#pragma unroll
        for (int ks = 0; ks < 2; ks++)
#pragma unroll
            for (int nt = 0; nt < 2; nt++)
#pragma unroll
                for (int m = 0; m < 4; m++)
                    mma_k16(acc[m][nt], A[ks][m][0], A[ks][m][1], A[ks][m][2], A[ks][m][3],
                            Bf[nt][ks][0], Bf[nt][ks][1]);

#pragma unroll
        for (int m = 0; m < 4; m++)
#pragma unroll
            for (int nt = 0; nt < 2; nt++) {
                int c = m * 16 + g4;
                int p = p0 + ph + nt * 8 + 2 * tg;
                size_t o1 = (size_t)c * HW_ + p;
                size_t o2 = (size_t)(c + 8) * HW_ + p;
                float2 r1 = make_float2(acc[m][nt][0] + xv[m][nt][0].x,
                                        acc[m][nt][1] + xv[m][nt][0].y);
                float2 r2 = make_float2(acc[m][nt][2] + xv[m][nt][1].x,
                                        acc[m][nt][3] + xv[m][nt][1].y);
                *reinterpret_cast<float2*>(&outb[o1]) = r1;
                *reinterpret_cast<float2*>(&outb[o2]) = r2;
            }
    }
}

// ---------------- launch ----------------
extern "C" void kernel_launch(void* const* d_in, const int* in_sizes, int n_in,
                              void* d_out, int out_size)
{
    const float* x     = (const float*)d_in[0];
    const float* Wt    = (const float*)d_in[1];
    const float* Wp    = (const float*)d_in[2];
    const float* Wg    = (const float*)d_in[3];
    const float* Wo    = (const float*)d_in[4];
    const float* gamma = (const float*)d_in[5];
    float* out = (float*)d_out;

    proj_kernel<<<dim3(32, 16), 256>>>(x, Wt, Wp, Wg);

    cudaFuncSetAttribute(attn_out_kernel, cudaFuncAttributeMaxDynamicSharedMemorySize, ATTN_SMEM);
    attn_out_kernel<<<dim3(16, 16), 256, ATTN_SMEM>>>(x, Wo, gamma, out);
}